// round 1
// baseline (speedup 1.0000x reference)
#include <cuda_runtime.h>

#define BLOCK 256
#define WBUF_F 6544                    // max phase weight floats (node phase)
#define SMEM_BYTES ((WBUF_F + 64 * BLOCK) * 4)

typedef unsigned long long ull;

__device__ __forceinline__ ull bcast2(float x) {
    ull r; unsigned u = __float_as_uint(x);
    asm("mov.b64 %0, {%1, %1};" : "=l"(r) : "r"(u));
    return r;
}
__device__ __forceinline__ void fma2(ull &a, ull x, ull w) {
    asm("fma.rn.f32x2 %0, %1, %2, %0;" : "+l"(a) : "l"(x), "l"(w));
}
__device__ __forceinline__ float2 unpk(ull a) {
    unsigned x, y;
    asm("mov.b64 {%0, %1}, %2;" : "=r"(x), "=r"(y) : "l"(a));
    return make_float2(__uint_as_float(x), __uint_as_float(y));
}

// init NACC f32x2 accumulators from smem bias (8B-aligned)
template<int NACC>
__device__ __forceinline__ void acc_init(ull *acc, const float *b) {
    const ull *bb = (const ull *)b;
#pragma unroll
    for (int p = 0; p < NACC; p++) acc[p] = bb[p];
}

// one input element against a weight row of 2*NACC outputs (row 16B-aligned)
template<int NACC>
__device__ __forceinline__ void fma_row(ull *acc, float xin, const float *wrow) {
    ull x = bcast2(xin);
#pragma unroll
    for (int p = 0; p < NACC; p += 2) {
        ulonglong2 w = *(const ulonglong2 *)(wrow + 2 * p);  // LDS.128 broadcast
        fma2(acc[p], x, w.x);
        fma2(acc[p + 1], x, w.y);
    }
}

__device__ __forceinline__ void fma_row1(ull &acc, float xin, const float *wrow) {
    ull x = bcast2(xin);
    ull w = *(const ull *)wrow;  // LDS.64 broadcast (2 outputs)
    fma2(acc, x, w);
}

// dense layer, 64 inputs streamed from per-thread smem column (stride BLOCK)
template<int NACC>
__device__ __forceinline__ void dense64_smem(ull *acc, const float *__restrict__ W,
                                             const float *__restrict__ hin) {
#pragma unroll 8
    for (int i = 0; i < 64; i++) fma_row<NACC>(acc, hin[i * BLOCK], W + i * 2 * NACC);
}

// dense layer, IN inputs from registers (fully unrolled: reg-array indexing)
template<int NACC, int IN>
__device__ __forceinline__ void dense_regs(ull *acc, const float *__restrict__ W,
                                           const float *in) {
#pragma unroll
    for (int i = 0; i < IN; i++) fma_row<NACC>(acc, in[i], W + i * 2 * NACC);
}

template<int NACC>
__device__ __forceinline__ void relu_store(const ull *acc, float *hout) {
#pragma unroll
    for (int p = 0; p < NACC; p++) {
        float2 f = unpk(acc[p]);
        hout[(2 * p) * BLOCK] = fmaxf(f.x, 0.f);
        hout[(2 * p + 1) * BLOCK] = fmaxf(f.y, 0.f);
    }
}

__device__ __forceinline__ void cp16(float *dst, const float *__restrict__ src, int n, int tid) {
    float4 *d = (float4 *)dst;
    const float4 *s = (const float4 *)src;
    for (int i = tid; i < (n >> 2); i += BLOCK) d[i] = s[i];
}

__global__ __launch_bounds__(BLOCK, 2)
void gen_kernel(const float *__restrict__ z, const float *__restrict__ data,
                const float *__restrict__ glog, const float *__restrict__ glat,
                const float *__restrict__ gbin,
                const float *__restrict__ LW0, const float *__restrict__ Lb0,
                const float *__restrict__ LW1, const float *__restrict__ Lb1,
                const float *__restrict__ LW2, const float *__restrict__ Lb2,
                const float *__restrict__ NW0, const float *__restrict__ Nb0,
                const float *__restrict__ NW1, const float *__restrict__ Nb1,
                const float *__restrict__ NWf, const float *__restrict__ Nbf,
                const float *__restrict__ W7f, const float *__restrict__ b7f,
                float *__restrict__ out) {
    extern __shared__ float sm[];
    float *wb = sm;                 // phase weight buffer
    float *hst = sm + WBUF_F;       // [64][BLOCK] hidden stage
    const int tid = threadIdx.x;
    const int gid = blockIdx.x * BLOCK + tid;
    float *hcol = hst + tid;

    __shared__ int ksel[4];
    if (tid < 4) {
        const float *a = glog + tid * 8;
        const float *g = glat + tid * 8;
        float best = a[0] + g[0];
        int bi = 0;
#pragma unroll
        for (int k = 1; k < 8; k++) {
            float v = a[k] + g[k];
            if (v > best) { best = v; bi = k; }   // first-max wins, matches jnp.argmax
        }
        ksel[tid] = bi;
    }

    // var0 in regs + passthrough of data[:,0:32] to out[:,0:32]
    const float *drow = data + (size_t)gid * 113;
    float *orow = out + (size_t)gid * 113;
    float var[16];
#pragma unroll
    for (int c = 0; c < 16; c++) { float v = drow[c]; var[c] = v; orow[c] = v; }
#pragma unroll
    for (int c = 16; c < 32; c++) orow[c] = drow[c];

    float w[16];  // selected latent outputs, 4 per layer
    __syncthreads();  // ksel visible

    // ================= latent phase (per layer l) =================
    for (int l = 0; l < 4; l++) {
        // weights -> smem: W0[8][64] @0, b0 @512, W1[64][64] @576, b1 @4672,
        //                  W2sel[64][4] @4736, b2sel @4992
        cp16(wb + 0, LW0 + (size_t)l * 512, 512, tid);
        cp16(wb + 512, Lb0 + l * 64, 64, tid);
        cp16(wb + 576, LW1 + (size_t)l * 4096, 4096, tid);
        cp16(wb + 4672, Lb1 + l * 64, 64, tid);
        {
            int k = ksel[l];
            for (int i = tid; i < 64; i += BLOCK)
                *(float4 *)(wb + 4736 + 4 * i) =
                    *(const float4 *)(LW2 + ((size_t)(l * 64 + i)) * 32 + k * 4);
            if (tid < 4) wb[4992 + tid] = Lb2[l * 32 + ksel[l] * 4 + tid];
        }
        __syncthreads();

        float z8[8];
        {
            float4 za = *(const float4 *)(z + (size_t)gid * 32 + l * 8);
            float4 zb = *(const float4 *)(z + (size_t)gid * 32 + l * 8 + 4);
            z8[0] = za.x; z8[1] = za.y; z8[2] = za.z; z8[3] = za.w;
            z8[4] = zb.x; z8[5] = zb.y; z8[6] = zb.z; z8[7] = zb.w;
        }
        ull acc[32];
        acc_init<32>(acc, wb + 512);
        dense_regs<32, 8>(acc, wb + 0, z8);
        relu_store<32>(acc, hcol);

        acc_init<32>(acc, wb + 4672);
        dense64_smem<32>(acc, wb + 576, hcol);
        relu_store<32>(acc, hcol);

        ull a2[2];
        acc_init<2>(a2, wb + 4992);
        dense64_smem<2>(a2, wb + 4736, hcol);
        float2 f0 = unpk(a2[0]), f1 = unpk(a2[1]);
        w[l * 4 + 0] = f0.x; w[l * 4 + 1] = f0.y;
        w[l * 4 + 2] = f1.x; w[l * 4 + 3] = f1.y;
        __syncthreads();
    }

    // ================= node chain (j = 0..5, node = j+2) =================
    const int LAY[6] = {0, 1, 2, 3, 0, 1};  // PARENT_LAT - 1
    for (int j = 0; j < 6; j++) {
        // weights -> smem: W0[20][64] @0, b0 @1280, W1[64][64] @1344, b1 @5440,
        //                  Wf[64][16] (or W7f[64][2]) @5504, bf @6528
        cp16(wb + 0, NW0 + (size_t)j * 1280, 1280, tid);
        cp16(wb + 1280, Nb0 + j * 64, 64, tid);
        cp16(wb + 1344, NW1 + (size_t)j * 4096, 4096, tid);
        cp16(wb + 5440, Nb1 + j * 64, 64, tid);
        if (j < 5) {
            cp16(wb + 5504, NWf + (size_t)j * 1024, 1024, tid);
            cp16(wb + 6528, Nbf + j * 16, 16, tid);
        } else {
            cp16(wb + 5504, W7f, 128, tid);
            if (tid < 2) wb[6528 + tid] = b7f[tid];
        }
        __syncthreads();

        float in20[20];
        {
            int lw = LAY[j] * 4;
#pragma unroll
            for (int d = 0; d < 4; d++) in20[d] = w[lw + d];
#pragma unroll
            for (int d = 0; d < 16; d++) in20[4 + d] = var[d];
        }
        ull acc[32];
        acc_init<32>(acc, wb + 1280);
        dense_regs<32, 20>(acc, wb + 0, in20);
        relu_store<32>(acc, hcol);

        acc_init<32>(acc, wb + 5440);
        dense64_smem<32>(acc, wb + 1344, hcol);
        relu_store<32>(acc, hcol);

        if (j < 5) {
            ull a8[8];
            acc_init<8>(a8, wb + 6528);
            dense64_smem<8>(a8, wb + 5504, hcol);
            int obase = 16 * (j + 2);
#pragma unroll
            for (int p = 0; p < 8; p++) {
                float2 f = unpk(a8[p]);
                var[2 * p] = f.x; var[2 * p + 1] = f.y;
                orow[obase + 2 * p] = f.x;
                orow[obase + 2 * p + 1] = f.y;
            }
        } else {
            ull a1 = ((const ull *)(wb + 6528))[0];
#pragma unroll 8
            for (int i = 0; i < 64; i++) fma_row1(a1, hcol[i * BLOCK], wb + 5504 + 2 * i);
            float2 v = unpk(a1);
            float p0 = 1.0f / (1.0f + expf(-v.x));
            float p1 = 1.0f / (1.0f + expf(-v.y));
            float g0 = gbin[(size_t)gid * 2 + 0];
            float g1 = gbin[(size_t)gid * 2 + 1];
            // straight-through binary one-hot forwards to exact hard argmax;
            // first index wins ties (jnp.argmax semantics)
            orow[112] = (p0 + g0 >= p1 + g1) ? 1.0f : 0.0f;
        }
        __syncthreads();
    }
}

extern "C" void kernel_launch(void *const *d_in, const int *in_sizes, int n_in,
                              void *d_out, int out_size) {
    (void)in_sizes; (void)n_in; (void)out_size;
    const float *z    = (const float *)d_in[0];
    const float *data = (const float *)d_in[1];
    const float *glog = (const float *)d_in[2];
    const float *glat = (const float *)d_in[3];
    const float *gbin = (const float *)d_in[4];
    const float *LW0  = (const float *)d_in[5];
    const float *Lb0  = (const float *)d_in[6];
    const float *LW1  = (const float *)d_in[7];
    const float *Lb1  = (const float *)d_in[8];
    const float *LW2  = (const float *)d_in[9];
    const float *Lb2  = (const float *)d_in[10];
    const float *NW0  = (const float *)d_in[11];
    const float *Nb0  = (const float *)d_in[12];
    const float *NW1  = (const float *)d_in[13];
    const float *Nb1  = (const float *)d_in[14];
    const float *NWf  = (const float *)d_in[15];
    const float *Nbf  = (const float *)d_in[16];
    const float *W7f  = (const float *)d_in[17];
    const float *b7f  = (const float *)d_in[18];
    float *out = (float *)d_out;

    cudaFuncSetAttribute(gen_kernel, cudaFuncAttributeMaxDynamicSharedMemorySize, SMEM_BYTES);
    gen_kernel<<<131072 / BLOCK, BLOCK, SMEM_BYTES>>>(
        z, data, glog, glat, gbin, LW0, Lb0, LW1, Lb1, LW2, Lb2,
        NW0, Nb0, NW1, Nb1, NWf, Nbf, W7f, b7f, out);
}